// round 15
// baseline (speedup 1.0000x reference)
#include <cuda_runtime.h>
#include <cuda_fp16.h>
#include <stdint.h>

#define NE 8
#define DD 1024
#define RR 64
#define TT 128
#define MAXN 16384
#define S1B 144         // fc1 smem row stride BYTES (64 fp16 = 128B data + 16 pad)
#define S2B 144         // fc2 smem row stride BYTES
#define B1SZ 27648      // fc1 buffer: A 128*144 + B 64*144
#define B1_BOFF 18432   // B tile offset inside fc1 buffer
#define B2SZ 18432      // fc2 W buffer: 128*144
#define HS_OFF 55296    // Hs offset
#define SMEM_TOTAL 73728

// ------------------------- device scratch ----------------------------------
__device__ int   g_counts[NE];
__device__ int   g_tok[NE * MAXN];          // encoded tok*2 + k
__device__ float g_gate[NE * MAXN];
__device__ __align__(16) unsigned short g_scratch_h[2u * MAXN * DD]; // 64 MB
__device__ __align__(16) unsigned short g_xh[(size_t)MAXN * DD];     // 32 MB fp16 x
__device__ __align__(16) unsigned short g_w1h[NE * RR * DD];         // 1 MB fp16 W1
__device__ __align__(16) unsigned short g_w2h[NE * DD * RR];         // 1 MB fp16 W2

// ------------------------- helpers -----------------------------------------
__device__ __forceinline__ uint32_t smem_u32(const void* p) {
    uint32_t a;
    asm("{ .reg .u64 t; cvta.to.shared.u64 t, %1; cvt.u32.u64 %0, t; }"
        : "=r"(a) : "l"(p));
    return a;
}
__device__ __forceinline__ void ldsm4(uint32_t* r, uint32_t addr) {
    asm volatile("ldmatrix.sync.aligned.m8n8.x4.shared.b16 {%0,%1,%2,%3}, [%4];"
                 : "=r"(r[0]), "=r"(r[1]), "=r"(r[2]), "=r"(r[3]) : "r"(addr));
}
__device__ __forceinline__ void mma16816(float* c, const uint32_t* a,
                                         const uint32_t* b) {
    asm volatile("mma.sync.aligned.m16n8k16.row.col.f32.f16.f16.f32 "
                 "{%0,%1,%2,%3}, {%4,%5,%6,%7}, {%8,%9}, {%0,%1,%2,%3};"
                 : "+f"(c[0]), "+f"(c[1]), "+f"(c[2]), "+f"(c[3])
                 : "r"(a[0]), "r"(a[1]), "r"(a[2]), "r"(a[3]),
                   "r"(b[0]), "r"(b[1]));
}
__device__ __forceinline__ uint32_t h2(float a, float b) {
    __half2 v = __floats2half2_rn(a, b);
    return *(uint32_t*)&v;
}

// ---------------------------------------------------------------------------
// pack_w: W1/W2 fp32 -> fp16 (runs once, tiny).
// ---------------------------------------------------------------------------
__global__ void pack_w_kernel(const float* __restrict__ W1,
                              const float* __restrict__ W2) {
    int idx = blockIdx.x * 256 + threadIdx.x;
    const int n1 = NE * RR * DD / 4;          // 131072 float4
    if (idx < n1) {
        float4 v = ((const float4*)W1)[idx];
        ((uint2*)g_w1h)[idx] = make_uint2(h2(v.x, v.y), h2(v.z, v.w));
    } else {
        idx -= n1;
        float4 v = ((const float4*)W2)[idx];
        ((uint2*)g_w2h)[idx] = make_uint2(h2(v.x, v.y), h2(v.z, v.w));
    }
}

// ---------------------------------------------------------------------------
// Router (R12 structure, verified ~39us) + fused fp16 x emission: the rows
// are already in registers, so pack+store them to g_xh for the expert kernel.
// ---------------------------------------------------------------------------
__global__ void router_kernel(const float* __restrict__ x,
                              const float* __restrict__ Wg,
                              const float* __restrict__ bg, int N) {
    __shared__ float4 sWg[NE * 256];
    int t = threadIdx.x;
    const float4* Wg4 = (const float4*)Wg;
    for (int i = t; i < NE * 256; i += 256) sWg[i] = Wg4[i];
    __syncthreads();

    int warp = t >> 5, lane = t & 31;
    for (int it = 0; it < 2; it++) {
        int tokA = blockIdx.x * 32 + warp * 4 + it * 2;
        if (tokA >= N) break;
        int tokB = tokA + 1;
        bool hasB = tokB < N;
        const float4* xrA = (const float4*)(x + (size_t)tokA * DD);
        const float4* xrB = (const float4*)(x + (size_t)(hasB ? tokB : tokA) * DD);
        float acc[2][NE];
#pragma unroll
        for (int i = 0; i < 2; i++)
#pragma unroll
            for (int e = 0; e < NE; e++) acc[i][e] = 0.f;
#pragma unroll
        for (int i = 0; i < 8; i++) {
            float4 xa = xrA[i * 32 + lane];
            float4 xb = xrB[i * 32 + lane];
            // fp16 copy of x for the expert kernel
            *(uint2*)(g_xh + (size_t)tokA * DD + (i * 32 + lane) * 4) =
                make_uint2(h2(xa.x, xa.y), h2(xa.z, xa.w));
            if (hasB)
                *(uint2*)(g_xh + (size_t)tokB * DD + (i * 32 + lane) * 4) =
                    make_uint2(h2(xb.x, xb.y), h2(xb.z, xb.w));
#pragma unroll
            for (int e = 0; e < NE; e++) {
                float4 w = sWg[e * 256 + i * 32 + lane];
                acc[0][e] = fmaf(xa.x, w.x, acc[0][e]);
                acc[0][e] = fmaf(xa.y, w.y, acc[0][e]);
                acc[0][e] = fmaf(xa.z, w.z, acc[0][e]);
                acc[0][e] = fmaf(xa.w, w.w, acc[0][e]);
                acc[1][e] = fmaf(xb.x, w.x, acc[1][e]);
                acc[1][e] = fmaf(xb.y, w.y, acc[1][e]);
                acc[1][e] = fmaf(xb.z, w.z, acc[1][e]);
                acc[1][e] = fmaf(xb.w, w.w, acc[1][e]);
            }
        }
#pragma unroll
        for (int i = 0; i < 2; i++)
#pragma unroll
            for (int e = 0; e < NE; e++) {
#pragma unroll
                for (int off = 16; off; off >>= 1)
                    acc[i][e] += __shfl_xor_sync(0xffffffffu, acc[i][e], off);
            }
        if (lane == 0) {
#pragma unroll
            for (int i = 0; i < 2; i++) {
                int tok = tokA + i;
                if (tok >= N) break;
                float l[NE];
#pragma unroll
                for (int e = 0; e < NE; e++) l[e] = acc[i][e] + bg[e];
                int i0 = 0;
#pragma unroll
                for (int e = 1; e < NE; e++) if (l[e] > l[i0]) i0 = e;
                int i1 = (i0 == 0) ? 1 : 0;
#pragma unroll
                for (int e = 0; e < NE; e++) if (e != i0 && l[e] > l[i1]) i1 = e;
                float ex = expf(l[i1] - l[i0]);
                float inv = 1.f / (1.f + ex);
                int p0 = atomicAdd(&g_counts[i0], 1);
                g_tok[i0 * MAXN + p0]  = tok * 2;
                g_gate[i0 * MAXN + p0] = inv;
                int p1 = atomicAdd(&g_counts[i1], 1);
                g_tok[i1 * MAXN + p1]  = tok * 2 + 1;
                g_gate[i1 * MAXN + p1] = ex * inv;
            }
        }
    }
}

// ---------------------------------------------------------------------------
// Expert kernel: pure fp16 mma; ALL staging is uint4 LDG->STS of pre-packed
// fp16 (no conversions in the hot loop). fp16 scratch stores.
// ---------------------------------------------------------------------------
__global__ void __launch_bounds__(256, 1)
expert_kernel() {
    extern __shared__ char dynsm[];
    __shared__ int   s_tok[TT];
    __shared__ float s_gate[TT];

    int e = blockIdx.x, tile = blockIdx.y;
    int cnt = g_counts[e];
    int base = tile * TT;
    if (base >= cnt) return;
    int nt = min(TT, cnt - base);

    int t = threadIdx.x, wid = t >> 5, l = t & 31;
    int wm = wid & 3, wn = wid >> 2;   // warp grid 4(M) x 2(N)

    if (t < TT) {
        if (t < nt) {
            s_tok[t]  = g_tok[e * MAXN + base + t];
            s_gate[t] = g_gate[e * MAXN + base + t];
        } else {
            s_tok[t]  = g_tok[e * MAXN + base];
            s_gate[t] = 0.f;
        }
    }
    __syncthreads();

    char* bufs = dynsm;
    char* Hs   = dynsm + HS_OFF;
    const unsigned short* W1e = g_w1h + (size_t)e * RR * DD;
    const unsigned short* W2e = g_w2h + (size_t)e * DD * RR;

    uint32_t a1_lo = (uint32_t)(((l & 7) + ((l >> 3) & 1) * 8) * S1B + (l >> 4) * 16);
    uint32_t b1_lo = (uint32_t)(((l & 7) + (l >> 4) * 8) * S1B + ((l >> 3) & 1) * 16);
    uint32_t a2_lo = (uint32_t)(((l & 7) + ((l >> 3) & 1) * 8) * S2B + (l >> 4) * 16);
    uint32_t b2_lo = (uint32_t)(((l & 7) + (l >> 4) * 8) * S2B + ((l >> 3) & 1) * 16);
    uint32_t bufs_a = smem_u32(bufs);

    // ================= fc1: 16 chunks of 64 k =================
    float acc[2][4][4];
#pragma unroll
    for (int i = 0; i < 2; i++)
#pragma unroll
        for (int j = 0; j < 4; j++)
#pragma unroll
            for (int k = 0; k < 4; k++) acc[i][j][k] = 0.f;

    uint4 qa[4], qb[2];
    auto ldg1 = [&](int c) {
#pragma unroll
        for (int j = 0; j < 4; j++) {
            int idx = t + j * 256;
            int r = idx >> 3, u = idx & 7;
            int tok = s_tok[r] >> 1;
            qa[j] = *(const uint4*)(g_xh + (size_t)tok * DD + c * 64 + u * 8);
        }
#pragma unroll
        for (int j = 0; j < 2; j++) {
            int idx = t + j * 256;
            int r = idx >> 3, u = idx & 7;
            qb[j] = *(const uint4*)(W1e + (size_t)r * DD + c * 64 + u * 8);
        }
    };
    auto sts1 = [&](int buf) {
        char* As = bufs + buf * B1SZ;
        char* Bs = As + B1_BOFF;
#pragma unroll
        for (int j = 0; j < 4; j++) {
            int idx = t + j * 256;
            int r = idx >> 3, u = idx & 7;
            *(uint4*)(As + r * S1B + u * 16) = qa[j];
        }
#pragma unroll
        for (int j = 0; j < 2; j++) {
            int idx = t + j * 256;
            int r = idx >> 3, u = idx & 7;
            *(uint4*)(Bs + r * S1B + u * 16) = qb[j];
        }
    };

    ldg1(0); sts1(0);
    __syncthreads();

    for (int c = 0; c < 16; c++) {
        int buf = c & 1;
        if (c + 1 < 16) ldg1(c + 1);
        uint32_t Aaddr = bufs_a + buf * B1SZ;
        uint32_t Baddr = Aaddr + B1_BOFF;
#pragma unroll
        for (int kk = 0; kk < 4; kk++) {
            uint32_t a[2][4], b[2][4];
#pragma unroll
            for (int mt = 0; mt < 2; mt++)
                ldsm4(a[mt], Aaddr + (wm * 32 + mt * 16) * S1B + kk * 32 + a1_lo);
#pragma unroll
            for (int pr = 0; pr < 2; pr++)
                ldsm4(b[pr], Baddr + (wn * 32 + pr * 16) * S1B + kk * 32 + b1_lo);
#pragma unroll
            for (int mt = 0; mt < 2; mt++)
#pragma unroll
                for (int ntl = 0; ntl < 4; ntl++)
                    mma16816(acc[mt][ntl], a[mt], &b[ntl >> 1][(ntl & 1) * 2]);
        }
        if (c + 1 < 16) sts1((c + 1) & 1);
        __syncthreads();
    }

    // ============ epilogue: gelu*gate*2 -> fp16 H in smem ============
#pragma unroll
    for (int mt = 0; mt < 2; mt++) {
#pragma unroll
        for (int ntl = 0; ntl < 4; ntl++) {
#pragma unroll
            for (int half = 0; half < 2; half++) {
                int r = wm * 32 + mt * 16 + half * 8 + (l >> 2);
                float gs = s_gate[r] * 2.0f;   // SCALING = 128/64
                float v0 = acc[mt][ntl][half * 2 + 0];
                float v1 = acc[mt][ntl][half * 2 + 1];
                float g0 = 0.5f * v0 * (1.f + erff(v0 * 0.70710678118654752f)) * gs;
                float g1 = 0.5f * v1 * (1.f + erff(v1 * 0.70710678118654752f)) * gs;
                int n = wn * 32 + ntl * 8 + (l & 3) * 2;
                *(uint32_t*)(Hs + r * S2B + n * 2) = h2(g0, g1);
            }
        }
    }
    __syncthreads();

    // ================= fc2: 8 chunks of 128 output cols (K=64) =============
    uint32_t HsA = smem_u32(Hs);
    uint4 qw[4];
    auto ldg2 = [&](int nch) {
#pragma unroll
        for (int j = 0; j < 4; j++) {
            int idx = t + j * 256;
            int r = idx >> 3, u = idx & 7;
            qw[j] = *(const uint4*)(W2e + (size_t)(nch * TT + r) * RR + u * 8);
        }
    };
    auto sts2 = [&](int buf) {
        char* Ws = bufs + buf * B2SZ;
#pragma unroll
        for (int j = 0; j < 4; j++) {
            int idx = t + j * 256;
            int r = idx >> 3, u = idx & 7;
            *(uint4*)(Ws + r * S2B + u * 16) = qw[j];
        }
    };

    ldg2(0); sts2(0);
    __syncthreads();

    for (int n = 0; n < 8; n++) {
        int buf = n & 1;
        if (n + 1 < 8) ldg2(n + 1);
        float acc2[2][8][4];
#pragma unroll
        for (int i = 0; i < 2; i++)
#pragma unroll
            for (int j = 0; j < 8; j++)
#pragma unroll
                for (int k = 0; k < 4; k++) acc2[i][j][k] = 0.f;

        uint32_t Waddr = bufs_a + buf * B2SZ;
#pragma unroll
        for (int kk = 0; kk < 4; kk++) {
            uint32_t a[2][4], b[4][4];
#pragma unroll
            for (int mt = 0; mt < 2; mt++)
                ldsm4(a[mt], HsA + (wm * 32 + mt * 16) * S2B + kk * 32 + a2_lo);
#pragma unroll
            for (int pr = 0; pr < 4; pr++)
                ldsm4(b[pr], Waddr + (wn * 64 + pr * 16) * S2B + kk * 32 + b2_lo);
#pragma unroll
            for (int mt = 0; mt < 2; mt++)
#pragma unroll
                for (int ntl = 0; ntl < 8; ntl++)
                    mma16816(acc2[mt][ntl], a[mt], &b[ntl >> 1][(ntl & 1) * 2]);
        }
        // store to fp16 scratch
#pragma unroll
        for (int mt = 0; mt < 2; mt++) {
#pragma unroll
            for (int half = 0; half < 2; half++) {
                int r = wm * 32 + mt * 16 + half * 8 + (l >> 2);
                if (r < nt) {
                    int slot = s_tok[r];
                    unsigned short* dst = g_scratch_h + (size_t)slot * DD
                                        + n * 128 + wn * 64 + (l & 3) * 2;
#pragma unroll
                    for (int ntl = 0; ntl < 8; ntl++)
                        *(uint32_t*)(dst + ntl * 8) =
                            h2(acc2[mt][ntl][half * 2 + 0],
                               acc2[mt][ntl][half * 2 + 1]);
                }
            }
        }
        if (n + 1 < 8) sts2((n + 1) & 1);
        __syncthreads();
    }
}

// ---------------------------------------------------------------------------
// Combine: out[tok] = fp32(scratch_h[tok,0]) + fp32(scratch_h[tok,1])
// ---------------------------------------------------------------------------
__global__ void combine_kernel(float* __restrict__ out, int N) {
    int i = blockIdx.x * blockDim.x + threadIdx.x;
    int total = N * (DD / 8);
    if (i >= total) return;
    int tok = i >> 7;
    int g   = i & 127;
    const uint4* pa = (const uint4*)(g_scratch_h + ((size_t)tok * 2) * DD + g * 8);
    const uint4* pb = (const uint4*)(g_scratch_h + ((size_t)tok * 2 + 1) * DD + g * 8);
    uint4 ua = *pa, ub = *pb;
    const __half2* ha = (const __half2*)&ua;
    const __half2* hb = (const __half2*)&ub;
    float4 o0, o1;
    float2 s0 = __half22float2(ha[0]), t0 = __half22float2(hb[0]);
    float2 s1 = __half22float2(ha[1]), t1 = __half22float2(hb[1]);
    float2 s2 = __half22float2(ha[2]), t2 = __half22float2(hb[2]);
    float2 s3 = __half22float2(ha[3]), t3 = __half22float2(hb[3]);
    o0.x = s0.x + t0.x; o0.y = s0.y + t0.y;
    o0.z = s1.x + t1.x; o0.w = s1.y + t1.y;
    o1.x = s2.x + t2.x; o1.y = s2.y + t2.y;
    o1.z = s3.x + t3.x; o1.w = s3.y + t3.y;
    float4* dst = (float4*)(out + (size_t)tok * DD + g * 8);
    dst[0] = o0;
    dst[1] = o1;
}

// ---------------------------------------------------------------------------
extern "C" void kernel_launch(void* const* d_in, const int* in_sizes, int n_in,
                              void* d_out, int out_size) {
    const float* x  = (const float*)d_in[0];
    const float* Wg = (const float*)d_in[1];
    const float* bg = (const float*)d_in[2];
    const float* W1 = (const float*)d_in[3];
    const float* W2 = (const float*)d_in[4];
    float* out = (float*)d_out;
    int N = in_sizes[0] / DD;

    cudaFuncSetAttribute(expert_kernel,
                         cudaFuncAttributeMaxDynamicSharedMemorySize, SMEM_TOTAL);

    void* counts_ptr = nullptr;
    cudaGetSymbolAddress(&counts_ptr, g_counts);
    cudaMemsetAsync(counts_ptr, 0, NE * sizeof(int), 0);

    pack_w_kernel<<<(2 * NE * RR * DD / 4 + 255) / 256, 256>>>(W1, W2);
    router_kernel<<<(N + 31) / 32, 256>>>(x, Wg, bg, N);

    dim3 egrid(NE, 128);
    expert_kernel<<<egrid, 256, SMEM_TOTAL>>>();

    int total = N * (DD / 8);
    combine_kernel<<<(total + 255) / 256, 256>>>(out, N);
}

// round 17
// speedup vs baseline: 1.0545x; 1.0545x over previous
#include <cuda_runtime.h>
#include <cuda_fp16.h>
#include <stdint.h>

#define NE 8
#define DD 1024
#define RR 64
#define TT 128
#define MAXN 16384
#define S1B 144         // fc1 smem row stride BYTES (64 fp16 = 128B data + 16 pad)
#define S2B 144         // fc2 smem row stride BYTES
#define B1SZ 27648      // fc1 buffer: A 128*144 + B 64*144
#define B1_BOFF 18432   // B tile offset inside fc1 buffer
#define B2SZ 18432      // fc2 W buffer: 128*144
#define HS_OFF 55296    // Hs offset
#define SMEM_TOTAL 73728

// ------------------------- device scratch ----------------------------------
__device__ int   g_counts[NE];
__device__ int   g_tok[NE * MAXN];          // encoded tok*2 + k
__device__ float g_gate[NE * MAXN];
__device__ __align__(16) unsigned short g_scratch_h[2u * MAXN * DD]; // 64 MB
__device__ __align__(16) unsigned short g_xh[(size_t)MAXN * DD];     // 32 MB fp16 x
__device__ __align__(16) unsigned short g_w1h[NE * RR * DD];         // 1 MB fp16 W1
__device__ __align__(16) unsigned short g_w2h[NE * DD * RR];         // 1 MB fp16 W2

// ------------------------- helpers -----------------------------------------
__device__ __forceinline__ uint32_t smem_u32(const void* p) {
    uint32_t a;
    asm("{ .reg .u64 t; cvta.to.shared.u64 t, %1; cvt.u32.u64 %0, t; }"
        : "=r"(a) : "l"(p));
    return a;
}
__device__ __forceinline__ void ldsm4(uint32_t* r, uint32_t addr) {
    asm volatile("ldmatrix.sync.aligned.m8n8.x4.shared.b16 {%0,%1,%2,%3}, [%4];"
                 : "=r"(r[0]), "=r"(r[1]), "=r"(r[2]), "=r"(r[3]) : "r"(addr));
}
__device__ __forceinline__ void mma16816(float* c, const uint32_t* a,
                                         const uint32_t* b) {
    asm volatile("mma.sync.aligned.m16n8k16.row.col.f32.f16.f16.f32 "
                 "{%0,%1,%2,%3}, {%4,%5,%6,%7}, {%8,%9}, {%0,%1,%2,%3};"
                 : "+f"(c[0]), "+f"(c[1]), "+f"(c[2]), "+f"(c[3])
                 : "r"(a[0]), "r"(a[1]), "r"(a[2]), "r"(a[3]),
                   "r"(b[0]), "r"(b[1]));
}
__device__ __forceinline__ uint32_t h2(float a, float b) {
    __half2 v = __floats2half2_rn(a, b);
    return *(uint32_t*)&v;
}

// ---------------------------------------------------------------------------
// pack_w: W1/W2 fp32 -> fp16 (runs once, tiny).
// ---------------------------------------------------------------------------
__global__ void pack_w_kernel(const float* __restrict__ W1,
                              const float* __restrict__ W2) {
    int idx = blockIdx.x * 256 + threadIdx.x;
    const int n1 = NE * RR * DD / 4;          // 131072 float4
    if (idx < n1) {
        float4 v = ((const float4*)W1)[idx];
        ((uint2*)g_w1h)[idx] = make_uint2(h2(v.x, v.y), h2(v.z, v.w));
    } else {
        idx -= n1;
        float4 v = ((const float4*)W2)[idx];
        ((uint2*)g_w2h)[idx] = make_uint2(h2(v.x, v.y), h2(v.z, v.w));
    }
}

// ---------------------------------------------------------------------------
// Router: ONE token pair per warp (16 tokens/block, grid N/16=1024) so the
// grid fills ~7 blocks/SM instead of 3.5 -> latency actually hidden.
// Fused fp16 x emission for the expert kernel.
// ---------------------------------------------------------------------------
__global__ void router_kernel(const float* __restrict__ x,
                              const float* __restrict__ Wg,
                              const float* __restrict__ bg, int N) {
    __shared__ float4 sWg[NE * 256];
    int t = threadIdx.x;
    const float4* Wg4 = (const float4*)Wg;
    for (int i = t; i < NE * 256; i += 256) sWg[i] = Wg4[i];
    __syncthreads();

    int warp = t >> 5, lane = t & 31;
    int tokA = blockIdx.x * 16 + warp * 2;
    if (tokA >= N) return;
    int tokB = tokA + 1;
    bool hasB = tokB < N;
    const float4* xrA = (const float4*)(x + (size_t)tokA * DD);
    const float4* xrB = (const float4*)(x + (size_t)(hasB ? tokB : tokA) * DD);
    float acc[2][NE];
#pragma unroll
    for (int i = 0; i < 2; i++)
#pragma unroll
        for (int e = 0; e < NE; e++) acc[i][e] = 0.f;
#pragma unroll
    for (int i = 0; i < 8; i++) {
        float4 xa = xrA[i * 32 + lane];
        float4 xb = xrB[i * 32 + lane];
        // fp16 copy of x for the expert kernel
        *(uint2*)(g_xh + (size_t)tokA * DD + (i * 32 + lane) * 4) =
            make_uint2(h2(xa.x, xa.y), h2(xa.z, xa.w));
        if (hasB)
            *(uint2*)(g_xh + (size_t)tokB * DD + (i * 32 + lane) * 4) =
                make_uint2(h2(xb.x, xb.y), h2(xb.z, xb.w));
#pragma unroll
        for (int e = 0; e < NE; e++) {
            float4 w = sWg[e * 256 + i * 32 + lane];
            acc[0][e] = fmaf(xa.x, w.x, acc[0][e]);
            acc[0][e] = fmaf(xa.y, w.y, acc[0][e]);
            acc[0][e] = fmaf(xa.z, w.z, acc[0][e]);
            acc[0][e] = fmaf(xa.w, w.w, acc[0][e]);
            acc[1][e] = fmaf(xb.x, w.x, acc[1][e]);
            acc[1][e] = fmaf(xb.y, w.y, acc[1][e]);
            acc[1][e] = fmaf(xb.z, w.z, acc[1][e]);
            acc[1][e] = fmaf(xb.w, w.w, acc[1][e]);
        }
    }
#pragma unroll
    for (int i = 0; i < 2; i++)
#pragma unroll
        for (int e = 0; e < NE; e++) {
#pragma unroll
            for (int off = 16; off; off >>= 1)
                acc[i][e] += __shfl_xor_sync(0xffffffffu, acc[i][e], off);
        }
    if (lane == 0) {
#pragma unroll
        for (int i = 0; i < 2; i++) {
            int tok = tokA + i;
            if (tok >= N) break;
            float l[NE];
#pragma unroll
            for (int e = 0; e < NE; e++) l[e] = acc[i][e] + bg[e];
            int i0 = 0;
#pragma unroll
            for (int e = 1; e < NE; e++) if (l[e] > l[i0]) i0 = e;
            int i1 = (i0 == 0) ? 1 : 0;
#pragma unroll
            for (int e = 0; e < NE; e++) if (e != i0 && l[e] > l[i1]) i1 = e;
            float ex = expf(l[i1] - l[i0]);
            float inv = 1.f / (1.f + ex);
            int p0 = atomicAdd(&g_counts[i0], 1);
            g_tok[i0 * MAXN + p0]  = tok * 2;
            g_gate[i0 * MAXN + p0] = inv;
            int p1 = atomicAdd(&g_counts[i1], 1);
            g_tok[i1 * MAXN + p1]  = tok * 2 + 1;
            g_gate[i1 * MAXN + p1] = ex * inv;
        }
    }
}

// ---------------------------------------------------------------------------
// Expert kernel: pure fp16 mma; ALL staging is uint4 LDG->STS of pre-packed
// fp16 (no conversions in the hot loop). fp16 scratch stores.
// ---------------------------------------------------------------------------
__global__ void __launch_bounds__(256, 1)
expert_kernel() {
    extern __shared__ char dynsm[];
    __shared__ int   s_tok[TT];
    __shared__ float s_gate[TT];

    int e = blockIdx.x, tile = blockIdx.y;
    int cnt = g_counts[e];
    int base = tile * TT;
    if (base >= cnt) return;
    int nt = min(TT, cnt - base);

    int t = threadIdx.x, wid = t >> 5, l = t & 31;
    int wm = wid & 3, wn = wid >> 2;   // warp grid 4(M) x 2(N)

    if (t < TT) {
        if (t < nt) {
            s_tok[t]  = g_tok[e * MAXN + base + t];
            s_gate[t] = g_gate[e * MAXN + base + t];
        } else {
            s_tok[t]  = g_tok[e * MAXN + base];
            s_gate[t] = 0.f;
        }
    }
    __syncthreads();

    char* bufs = dynsm;
    char* Hs   = dynsm + HS_OFF;
    const unsigned short* W1e = g_w1h + (size_t)e * RR * DD;
    const unsigned short* W2e = g_w2h + (size_t)e * DD * RR;

    uint32_t a1_lo = (uint32_t)(((l & 7) + ((l >> 3) & 1) * 8) * S1B + (l >> 4) * 16);
    uint32_t b1_lo = (uint32_t)(((l & 7) + (l >> 4) * 8) * S1B + ((l >> 3) & 1) * 16);
    uint32_t a2_lo = (uint32_t)(((l & 7) + ((l >> 3) & 1) * 8) * S2B + (l >> 4) * 16);
    uint32_t b2_lo = (uint32_t)(((l & 7) + (l >> 4) * 8) * S2B + ((l >> 3) & 1) * 16);
    uint32_t bufs_a = smem_u32(bufs);

    // ================= fc1: 16 chunks of 64 k =================
    float acc[2][4][4];
#pragma unroll
    for (int i = 0; i < 2; i++)
#pragma unroll
        for (int j = 0; j < 4; j++)
#pragma unroll
            for (int k = 0; k < 4; k++) acc[i][j][k] = 0.f;

    uint4 qa[4], qb[2];
    auto ldg1 = [&](int c) {
#pragma unroll
        for (int j = 0; j < 4; j++) {
            int idx = t + j * 256;
            int r = idx >> 3, u = idx & 7;
            int tok = s_tok[r] >> 1;
            qa[j] = *(const uint4*)(g_xh + (size_t)tok * DD + c * 64 + u * 8);
        }
#pragma unroll
        for (int j = 0; j < 2; j++) {
            int idx = t + j * 256;
            int r = idx >> 3, u = idx & 7;
            qb[j] = *(const uint4*)(W1e + (size_t)r * DD + c * 64 + u * 8);
        }
    };
    auto sts1 = [&](int buf) {
        char* As = bufs + buf * B1SZ;
        char* Bs = As + B1_BOFF;
#pragma unroll
        for (int j = 0; j < 4; j++) {
            int idx = t + j * 256;
            int r = idx >> 3, u = idx & 7;
            *(uint4*)(As + r * S1B + u * 16) = qa[j];
        }
#pragma unroll
        for (int j = 0; j < 2; j++) {
            int idx = t + j * 256;
            int r = idx >> 3, u = idx & 7;
            *(uint4*)(Bs + r * S1B + u * 16) = qb[j];
        }
    };

    ldg1(0); sts1(0);
    __syncthreads();

    for (int c = 0; c < 16; c++) {
        int buf = c & 1;
        if (c + 1 < 16) ldg1(c + 1);
        uint32_t Aaddr = bufs_a + buf * B1SZ;
        uint32_t Baddr = Aaddr + B1_BOFF;
#pragma unroll
        for (int kk = 0; kk < 4; kk++) {
            uint32_t a[2][4], b[2][4];
#pragma unroll
            for (int mt = 0; mt < 2; mt++)
                ldsm4(a[mt], Aaddr + (wm * 32 + mt * 16) * S1B + kk * 32 + a1_lo);
#pragma unroll
            for (int pr = 0; pr < 2; pr++)
                ldsm4(b[pr], Baddr + (wn * 32 + pr * 16) * S1B + kk * 32 + b1_lo);
#pragma unroll
            for (int mt = 0; mt < 2; mt++)
#pragma unroll
                for (int ntl = 0; ntl < 4; ntl++)
                    mma16816(acc[mt][ntl], a[mt], &b[ntl >> 1][(ntl & 1) * 2]);
        }
        if (c + 1 < 16) sts1((c + 1) & 1);
        __syncthreads();
    }

    // ============ epilogue: gelu*gate*2 -> fp16 H in smem ============
#pragma unroll
    for (int mt = 0; mt < 2; mt++) {
#pragma unroll
        for (int ntl = 0; ntl < 4; ntl++) {
#pragma unroll
            for (int half = 0; half < 2; half++) {
                int r = wm * 32 + mt * 16 + half * 8 + (l >> 2);
                float gs = s_gate[r] * 2.0f;   // SCALING = 128/64
                float v0 = acc[mt][ntl][half * 2 + 0];
                float v1 = acc[mt][ntl][half * 2 + 1];
                float g0 = 0.5f * v0 * (1.f + erff(v0 * 0.70710678118654752f)) * gs;
                float g1 = 0.5f * v1 * (1.f + erff(v1 * 0.70710678118654752f)) * gs;
                int n = wn * 32 + ntl * 8 + (l & 3) * 2;
                *(uint32_t*)(Hs + r * S2B + n * 2) = h2(g0, g1);
            }
        }
    }
    __syncthreads();

    // ================= fc2: 8 chunks of 128 output cols (K=64) =============
    uint32_t HsA = smem_u32(Hs);
    uint4 qw[4];
    auto ldg2 = [&](int nch) {
#pragma unroll
        for (int j = 0; j < 4; j++) {
            int idx = t + j * 256;
            int r = idx >> 3, u = idx & 7;
            qw[j] = *(const uint4*)(W2e + (size_t)(nch * TT + r) * RR + u * 8);
        }
    };
    auto sts2 = [&](int buf) {
        char* Ws = bufs + buf * B2SZ;
#pragma unroll
        for (int j = 0; j < 4; j++) {
            int idx = t + j * 256;
            int r = idx >> 3, u = idx & 7;
            *(uint4*)(Ws + r * S2B + u * 16) = qw[j];
        }
    };

    ldg2(0); sts2(0);
    __syncthreads();

    for (int n = 0; n < 8; n++) {
        int buf = n & 1;
        if (n + 1 < 8) ldg2(n + 1);
        float acc2[2][8][4];
#pragma unroll
        for (int i = 0; i < 2; i++)
#pragma unroll
            for (int j = 0; j < 8; j++)
#pragma unroll
                for (int k = 0; k < 4; k++) acc2[i][j][k] = 0.f;

        uint32_t Waddr = bufs_a + buf * B2SZ;
#pragma unroll
        for (int kk = 0; kk < 4; kk++) {
            uint32_t a[2][4], b[4][4];
#pragma unroll
            for (int mt = 0; mt < 2; mt++)
                ldsm4(a[mt], HsA + (wm * 32 + mt * 16) * S2B + kk * 32 + a2_lo);
#pragma unroll
            for (int pr = 0; pr < 4; pr++)
                ldsm4(b[pr], Waddr + (wn * 64 + pr * 16) * S2B + kk * 32 + b2_lo);
#pragma unroll
            for (int mt = 0; mt < 2; mt++)
#pragma unroll
                for (int ntl = 0; ntl < 8; ntl++)
                    mma16816(acc2[mt][ntl], a[mt], &b[ntl >> 1][(ntl & 1) * 2]);
        }
        // store to fp16 scratch
#pragma unroll
        for (int mt = 0; mt < 2; mt++) {
#pragma unroll
            for (int half = 0; half < 2; half++) {
                int r = wm * 32 + mt * 16 + half * 8 + (l >> 2);
                if (r < nt) {
                    int slot = s_tok[r];
                    unsigned short* dst = g_scratch_h + (size_t)slot * DD
                                        + n * 128 + wn * 64 + (l & 3) * 2;
#pragma unroll
                    for (int ntl = 0; ntl < 8; ntl++)
                        *(uint32_t*)(dst + ntl * 8) =
                            h2(acc2[mt][ntl][half * 2 + 0],
                               acc2[mt][ntl][half * 2 + 1]);
                }
            }
        }
        if (n + 1 < 8) sts2((n + 1) & 1);
        __syncthreads();
    }
}

// ---------------------------------------------------------------------------
// Combine: out[tok] = fp32(scratch_h[tok,0]) + fp32(scratch_h[tok,1])
// ---------------------------------------------------------------------------
__global__ void combine_kernel(float* __restrict__ out, int N) {
    int i = blockIdx.x * blockDim.x + threadIdx.x;
    int total = N * (DD / 8);
    if (i >= total) return;
    int tok = i >> 7;
    int g   = i & 127;
    const uint4* pa = (const uint4*)(g_scratch_h + ((size_t)tok * 2) * DD + g * 8);
    const uint4* pb = (const uint4*)(g_scratch_h + ((size_t)tok * 2 + 1) * DD + g * 8);
    uint4 ua = *pa, ub = *pb;
    const __half2* ha = (const __half2*)&ua;
    const __half2* hb = (const __half2*)&ub;
    float4 o0, o1;
    float2 s0 = __half22float2(ha[0]), t0 = __half22float2(hb[0]);
    float2 s1 = __half22float2(ha[1]), t1 = __half22float2(hb[1]);
    float2 s2 = __half22float2(ha[2]), t2 = __half22float2(hb[2]);
    float2 s3 = __half22float2(ha[3]), t3 = __half22float2(hb[3]);
    o0.x = s0.x + t0.x; o0.y = s0.y + t0.y;
    o0.z = s1.x + t1.x; o0.w = s1.y + t1.y;
    o1.x = s2.x + t2.x; o1.y = s2.y + t2.y;
    o1.z = s3.x + t3.x; o1.w = s3.y + t3.y;
    float4* dst = (float4*)(out + (size_t)tok * DD + g * 8);
    dst[0] = o0;
    dst[1] = o1;
}

// ---------------------------------------------------------------------------
extern "C" void kernel_launch(void* const* d_in, const int* in_sizes, int n_in,
                              void* d_out, int out_size) {
    const float* x  = (const float*)d_in[0];
    const float* Wg = (const float*)d_in[1];
    const float* bg = (const float*)d_in[2];
    const float* W1 = (const float*)d_in[3];
    const float* W2 = (const float*)d_in[4];
    float* out = (float*)d_out;
    int N = in_sizes[0] / DD;

    cudaFuncSetAttribute(expert_kernel,
                         cudaFuncAttributeMaxDynamicSharedMemorySize, SMEM_TOTAL);

    void* counts_ptr = nullptr;
    cudaGetSymbolAddress(&counts_ptr, g_counts);
    cudaMemsetAsync(counts_ptr, 0, NE * sizeof(int), 0);

    pack_w_kernel<<<(2 * NE * RR * DD / 4 + 255) / 256, 256>>>(W1, W2);
    router_kernel<<<(N + 15) / 16, 256>>>(x, Wg, bg, N);

    dim3 egrid(NE, 128);
    expert_kernel<<<egrid, 256, SMEM_TOTAL>>>();

    int total = N * (DD / 8);
    combine_kernel<<<(total + 255) / 256, 256>>>(out, N);
}